// round 5
// baseline (speedup 1.0000x reference)
#include <cuda_runtime.h>

#define NN 100000
#define EE 1600000
#define GG 128
#define HH 128
#define WALKN 16
#define PEDN 16
#define LL 5
#define OUTN 10

// ------------------- scratch (device globals: no allocs allowed) -------------------
__device__ __align__(16) float g_h[NN * HH];
__device__ __align__(16) float g_agg[NN * HH];
__device__ __align__(16) float g_t[NN * 2 * HH];
__device__ __align__(16) float g_z[NN * HH];
__device__ float g_rw[WALKN * NN];
__device__ float g_p[NN];
__device__ float g_np[NN];
__device__ float g_dinv[NN];
__device__ float g_ew[EE];
__device__ float g_deg[NN];
__device__ float g_cnt[GG];
__device__ float g_pe[NN * PEDN];
__device__ float g_base[HH];
__device__ float g_cs[HH];
__device__ float g_cq[HH];
__device__ float g_mu[HH];
__device__ float g_rs[HH];
__device__ float g_gsum[GG * HH];
__device__ int   g_edge[2 * EE];   // converted int32 row/col
__device__ int   g_batch[NN];      // converted int32 batch
__device__ int   g_flag[1];        // 1 -> inputs are int64

// ------------------- dtype detection / conversion -------------------
// int64 little-endian values in [0, 2^31) have all odd 32-bit words zero.
__global__ void k_detect(const int* __restrict__ e, int* flag) {
    if (threadIdx.x == 0) {
        int nz = 0;
        for (int i = 0; i < 256; i++) nz |= e[2 * i + 1];
        flag[0] = (nz == 0) ? 1 : 0;
    }
}

__global__ void k_cvt(const void* __restrict__ src, int n, const int* __restrict__ flag,
                      int* __restrict__ dst) {
    int i = blockIdx.x * blockDim.x + threadIdx.x;
    if (i >= n) return;
    if (flag[0]) dst[i] = (int)((const long long*)src)[i];
    else         dst[i] = ((const int*)src)[i];
}

// ------------------- small kernels -------------------
__global__ void k_init(float* deg, float* cnt) {
    int i = blockIdx.x * blockDim.x + threadIdx.x;
    if (i < NN) deg[i] = 1.0f;          // self-loop contributes 1 to every node's degree
    if (i < GG) cnt[i] = 0.0f;
}

__global__ void k_deg_scatter(const int* __restrict__ col, float* deg) {
    int e = blockIdx.x * blockDim.x + threadIdx.x;
    if (e < EE) atomicAdd(&deg[col[e]], 1.0f);
}

__global__ void k_cnt_scatter(const int* __restrict__ batch, float* cnt) {
    int n = blockIdx.x * blockDim.x + threadIdx.x;
    if (n < NN) atomicAdd(&cnt[batch[n]], 1.0f);
}

__global__ void k_dinv(float* dinv, const float* __restrict__ deg) {
    int n = blockIdx.x * blockDim.x + threadIdx.x;
    if (n < NN) dinv[n] = rsqrtf(deg[n]);   // deg >= 1 always
}

__global__ void k_ew(const int* __restrict__ row, const int* __restrict__ col,
                     const float* __restrict__ dinv, float* ew) {
    int e = blockIdx.x * blockDim.x + threadIdx.x;
    if (e < EE) ew[e] = dinv[row[e]] * dinv[col[e]];
}

__global__ void k_prob(const int* __restrict__ batch, const float* __restrict__ cnt, float* p) {
    int n = blockIdx.x * blockDim.x + threadIdx.x;
    if (n < NN) p[n] = 1.0f / fmaxf(cnt[batch[n]], 1.0f);
}

__global__ void k_rwpre(const float* __restrict__ p, float* rwk, float* np) {
    int n = blockIdx.x * blockDim.x + threadIdx.x;
    if (n < NN) { rwk[n] = p[n]; np[n] = 0.0f; }
}

__global__ void k_rwscat(const int* __restrict__ row, const int* __restrict__ col,
                         const float* __restrict__ ew, const float* __restrict__ p,
                         float* np) {
    int e = blockIdx.x * blockDim.x + threadIdx.x;
    if (e < EE) atomicAdd(&np[col[e]], p[row[e]] * ew[e]);
}

__global__ void k_rwcomb(const float* __restrict__ np, const float* __restrict__ dinv, float* p) {
    int n = blockIdx.x * blockDim.x + threadIdx.x;
    if (n < NN) {
        float pn = p[n];
        float d = dinv[n];
        p[n] = 0.9f * (np[n] + pn * d * d) + 0.1f * pn;  // self-loop folded in
    }
}

__global__ void k_pe(const float* __restrict__ rw, const float* __restrict__ pe_w,
                     const float* __restrict__ pe_b, float* pe) {
    __shared__ float sw[WALKN * PEDN];
    __shared__ float sb[PEDN];
    if (threadIdx.x < WALKN * PEDN) sw[threadIdx.x] = pe_w[threadIdx.x];
    if (threadIdx.x < PEDN) sb[threadIdx.x] = pe_b[threadIdx.x];
    __syncthreads();
    int n = blockIdx.x * blockDim.x + threadIdx.x;
    if (n >= NN) return;
    float acc[PEDN];
#pragma unroll
    for (int j = 0; j < PEDN; j++) acc[j] = sb[j];
#pragma unroll
    for (int k = 0; k < WALKN; k++) {
        float r = rw[k * NN + n];
#pragma unroll
        for (int j = 0; j < PEDN; j++) acc[j] += r * sw[k * PEDN + j];
    }
#pragma unroll
    for (int j = 0; j < PEDN; j++) pe[n * PEDN + j] = acc[j];
}

// base[o] = emb[0,:] @ proj_w[:128,o] + proj_b[o]   (all node embeddings identical)
__global__ void k_base(const float* __restrict__ emb, const float* __restrict__ proj_w,
                       const float* __restrict__ proj_b, float* base) {
    int o = threadIdx.x;
    float s = proj_b[o];
#pragma unroll 8
    for (int d = 0; d < 128; d++) s += emb[d] * proj_w[d * HH + o];
    base[o] = s;
}

__global__ void k_h0(const float* __restrict__ pe, const float* __restrict__ proj_w,
                     const float* __restrict__ base, float* h) {
    int idx = blockIdx.x * blockDim.x + threadIdx.x;
    if (idx >= NN * HH) return;
    int n = idx >> 7;
    int o = idx & 127;
    float s = base[o];
    const float* pw = proj_w + 128 * HH;   // rows 128..143 (PE part)
#pragma unroll
    for (int j = 0; j < PEDN; j++) s += pe[n * PEDN + j] * pw[j * HH + o];
    h[idx] = s;
}

__global__ void k_copy4(float4* __restrict__ dst, const float4* __restrict__ src, int n4) {
    int i = blockIdx.x * blockDim.x + threadIdx.x;
    if (i < n4) dst[i] = src[i];
}

// warp-per-edge gather + vector-reduce scatter (agg[col] += h[row])
__global__ void k_scatter(const int* __restrict__ row, const int* __restrict__ col,
                          const float* __restrict__ h, float* __restrict__ agg) {
    unsigned tid = blockIdx.x * blockDim.x + threadIdx.x;
    unsigned e = tid >> 5;
    if (e >= EE) return;
    int lane = tid & 31;
    int r = __ldg(row + e);
    int c = __ldg(col + e);
    float4 v = __ldg((const float4*)(h + (long)r * HH) + lane);
    float* dst = agg + (long)c * HH + lane * 4;
    asm volatile("red.global.add.v4.f32 [%0], {%1,%2,%3,%4};"
                 :: "l"(dst), "f"(v.x), "f"(v.y), "f"(v.z), "f"(v.w) : "memory");
}

// ------------------- tiled fp32 GEMM, W persisted in SMEM -------------------
template <int K, int NO, bool RELU, bool ADDRES>
__global__ void k_gemm(const float* __restrict__ A, const float* __restrict__ W,
                       const float* __restrict__ bias, const float* __restrict__ res,
                       float* __restrict__ C, int M) {
    constexpr int TM = (NO == 128) ? 64 : 32;
    constexpr int CG = NO / 4;           // column groups of 4
    constexpr int RT = TM / (512 / CG);  // rows per thread
    extern __shared__ float sm[];
    float* sW = sm;             // K*NO
    float* sA = sm + K * NO;    // TM*K

    for (int i = threadIdx.x; i < K * NO / 4; i += blockDim.x)
        ((float4*)sW)[i] = ((const float4*)W)[i];

    int ty = threadIdx.x / CG;
    int c0 = (threadIdx.x % CG) * 4;
    float b4[4];
#pragma unroll
    for (int j = 0; j < 4; j++) b4[j] = bias[c0 + j];

    int tiles = (M + TM - 1) / TM;
    for (int t0 = blockIdx.x; t0 < tiles; t0 += gridDim.x) {
        int m0 = t0 * TM;
        __syncthreads();
        for (int i = threadIdx.x; i < TM * K / 4; i += blockDim.x) {
            int r = i / (K / 4);
            int kk = i % (K / 4);
            float4 v = make_float4(0.f, 0.f, 0.f, 0.f);
            if (m0 + r < M) v = ((const float4*)(A + (long)(m0 + r) * K))[kk];
            ((float4*)(sA + r * K))[kk] = v;
        }
        __syncthreads();

        float acc[RT][4];
#pragma unroll
        for (int i = 0; i < RT; i++)
#pragma unroll
            for (int j = 0; j < 4; j++) acc[i][j] = 0.f;

#pragma unroll 4
        for (int k = 0; k < K; k++) {
            float4 w = *(const float4*)(sW + k * NO + c0);
#pragma unroll
            for (int i = 0; i < RT; i++) {
                float a = sA[(ty * RT + i) * K + k];
                acc[i][0] += a * w.x;
                acc[i][1] += a * w.y;
                acc[i][2] += a * w.z;
                acc[i][3] += a * w.w;
            }
        }

#pragma unroll
        for (int i = 0; i < RT; i++) {
            int r = m0 + ty * RT + i;
            if (r >= M) continue;
            float4 o;
            o.x = acc[i][0] + b4[0];
            o.y = acc[i][1] + b4[1];
            o.z = acc[i][2] + b4[2];
            o.w = acc[i][3] + b4[3];
            if (RELU) {
                o.x = fmaxf(o.x, 0.f); o.y = fmaxf(o.y, 0.f);
                o.z = fmaxf(o.z, 0.f); o.w = fmaxf(o.w, 0.f);
            }
            if (ADDRES) {
                float4 rv = *(const float4*)(res + (long)r * NO + c0);
                o.x += rv.x; o.y += rv.y; o.z += rv.z; o.w += rv.w;
            }
            *(float4*)(C + (long)r * NO + c0) = o;
        }
    }
}

// smem bytes needed by k_gemm<K,NO,...> — MUST mirror the kernel's TM formula.
static constexpr int gemm_smem(int K, int NO) {
    int TM = (NO == 128) ? 64 : 32;
    return (K * NO + TM * K) * 4;
}

// ------------------- batchnorm pieces -------------------
__global__ void k_zero_stats(float* cs, float* cq) {
    int i = threadIdx.x;
    if (i < HH) { cs[i] = 0.f; cq[i] = 0.f; }
}

__global__ void k_stats(const float* __restrict__ z, float* cs, float* cq) {
    int c = threadIdx.x;
    float s = 0.f, s2 = 0.f;
    for (int n = blockIdx.x; n < NN; n += gridDim.x) {
        float v = z[(long)n * HH + c];
        s += v;
        s2 += v * v;
    }
    atomicAdd(&cs[c], s);
    atomicAdd(&cq[c], s2);
}

__global__ void k_murs(const float* __restrict__ cs, const float* __restrict__ cq,
                       float* mu, float* rs) {
    int c = threadIdx.x;
    float m = cs[c] * (1.0f / NN);
    mu[c] = m;
    float v = cq[c] * (1.0f / NN) - m * m;
    rs[c] = rsqrtf(v + 1e-5f);
}

__global__ void k_bn_relu_res(const float* __restrict__ z, const float* __restrict__ mu,
                              const float* __restrict__ rs, const float* __restrict__ g,
                              const float* __restrict__ b, float* h) {
    int idx = blockIdx.x * blockDim.x + threadIdx.x;
    if (idx >= NN * HH) return;
    int c = idx & 127;
    float v = (z[idx] - mu[c]) * rs[c] * g[c] + b[c];
    h[idx] = h[idx] + fmaxf(v, 0.f);
}

__global__ void k_bn(const float* __restrict__ z, const float* __restrict__ mu,
                     const float* __restrict__ rs, const float* __restrict__ g,
                     const float* __restrict__ b, float* h) {
    int idx = blockIdx.x * blockDim.x + threadIdx.x;
    if (idx >= NN * HH) return;
    int c = idx & 127;
    h[idx] = (z[idx] - mu[c]) * rs[c] * g[c] + b[c];
}

// ------------------- pooling + head -------------------
__global__ void k_zero_gsum(float* gs) {
    int i = blockIdx.x * blockDim.x + threadIdx.x;
    if (i < GG * HH) gs[i] = 0.f;
}

// batch is sorted: contiguous row chunks per block, flush on graph change
__global__ void k_pool(const float* __restrict__ h, const int* __restrict__ batch,
                       float* gsum) {
    int c = threadIdx.x;
    int R = (NN + gridDim.x - 1) / gridDim.x;
    int n0 = blockIdx.x * R;
    int n1 = min(n0 + R, NN);
    if (n0 >= n1) return;
    float acc = 0.f;
    int cg = batch[n0];
    for (int n = n0; n < n1; n++) {
        int g = batch[n];
        if (g != cg) {
            atomicAdd(&gsum[cg * HH + c], acc);
            acc = 0.f;
            cg = g;
        }
        acc += h[(long)n * HH + c];
    }
    atomicAdd(&gsum[cg * HH + c], acc);
}

__global__ void k_head(const float* __restrict__ gsum, const float* __restrict__ cnt,
                       const float* __restrict__ w1, const float* __restrict__ b1,
                       const float* __restrict__ w2, const float* __restrict__ b2,
                       float* out) {
    __shared__ float gv[HH];
    __shared__ float hid[HH];
    int t = threadIdx.x;
    int gI = blockIdx.x;
    gv[t] = gsum[gI * HH + t] / fmaxf(cnt[gI], 1.0f);
    __syncthreads();
    float s = b1[t];
#pragma unroll 8
    for (int k = 0; k < HH; k++) s += gv[k] * w1[k * HH + t];
    hid[t] = fmaxf(s, 0.f);
    __syncthreads();
    if (t < OUTN) {
        float o = b2[t];
#pragma unroll 8
        for (int k = 0; k < HH; k++) o += hid[k] * w2[k * OUTN + t];
        out[gI * OUTN + t] = o;
    }
}

// ------------------- launcher -------------------
static inline int cdiv(long a, long b) { return (int)((a + b - 1) / b); }

extern "C" void kernel_launch(void* const* d_in, const int* in_sizes, int n_in,
                              void* d_out, int out_size) {
    // -------- input mapping: metadata may be reference-dict order or alphabetical --------
    const void *edge_raw, *batch_raw;
    const float *emb, *pe_w, *pe_b, *proj_w, *proj_b;
    const float *gin_w1, *gin_b1, *gin_w2, *gin_b2, *bn_g, *bn_b;
    const float *ffn_w1, *ffn_b1, *ffn_w2, *ffn_b2, *fbn_g, *fbn_b;
    const float *ow1, *ob1, *ow2, *ob2;

    if (in_sizes[1] == 2 * EE) {
        // dict order
        edge_raw  = d_in[1];  batch_raw = d_in[2];
        emb  = (const float*)d_in[3];  pe_w = (const float*)d_in[4];  pe_b = (const float*)d_in[5];
        proj_w = (const float*)d_in[6]; proj_b = (const float*)d_in[7];
        gin_w1 = (const float*)d_in[8]; gin_b1 = (const float*)d_in[9];
        gin_w2 = (const float*)d_in[10]; gin_b2 = (const float*)d_in[11];
        bn_g = (const float*)d_in[12]; bn_b = (const float*)d_in[13];
        ffn_w1 = (const float*)d_in[14]; ffn_b1 = (const float*)d_in[15];
        ffn_w2 = (const float*)d_in[16]; ffn_b2 = (const float*)d_in[17];
        fbn_g = (const float*)d_in[18]; fbn_b = (const float*)d_in[19];
        ow1 = (const float*)d_in[20]; ob1 = (const float*)d_in[21];
        ow2 = (const float*)d_in[22]; ob2 = (const float*)d_in[23];
    } else {
        // alphabetical order
        batch_raw = d_in[0];
        bn_b = (const float*)d_in[1]; bn_g = (const float*)d_in[2];
        edge_raw = d_in[3];
        emb = (const float*)d_in[4];
        ffn_b1 = (const float*)d_in[5]; ffn_b2 = (const float*)d_in[6];
        fbn_b = (const float*)d_in[7]; fbn_g = (const float*)d_in[8];
        ffn_w1 = (const float*)d_in[9]; ffn_w2 = (const float*)d_in[10];
        gin_b1 = (const float*)d_in[11]; gin_b2 = (const float*)d_in[12];
        gin_w1 = (const float*)d_in[13]; gin_w2 = (const float*)d_in[14];
        ob1 = (const float*)d_in[15]; ob2 = (const float*)d_in[16];
        ow1 = (const float*)d_in[17]; ow2 = (const float*)d_in[18];
        pe_b = (const float*)d_in[19]; pe_w = (const float*)d_in[20];
        proj_b = (const float*)d_in[21]; proj_w = (const float*)d_in[22];
    }
    float* out = (float*)d_out;

    float *h, *agg, *t, *z, *rw, *p, *np, *dinv, *ew, *deg, *cnt, *pe, *base;
    float *cs, *cq, *mu, *rs, *gsum;
    int *edge, *batch, *flag;
    cudaGetSymbolAddress((void**)&h, g_h);
    cudaGetSymbolAddress((void**)&agg, g_agg);
    cudaGetSymbolAddress((void**)&t, g_t);
    cudaGetSymbolAddress((void**)&z, g_z);
    cudaGetSymbolAddress((void**)&rw, g_rw);
    cudaGetSymbolAddress((void**)&p, g_p);
    cudaGetSymbolAddress((void**)&np, g_np);
    cudaGetSymbolAddress((void**)&dinv, g_dinv);
    cudaGetSymbolAddress((void**)&ew, g_ew);
    cudaGetSymbolAddress((void**)&deg, g_deg);
    cudaGetSymbolAddress((void**)&cnt, g_cnt);
    cudaGetSymbolAddress((void**)&pe, g_pe);
    cudaGetSymbolAddress((void**)&base, g_base);
    cudaGetSymbolAddress((void**)&cs, g_cs);
    cudaGetSymbolAddress((void**)&cq, g_cq);
    cudaGetSymbolAddress((void**)&mu, g_mu);
    cudaGetSymbolAddress((void**)&rs, g_rs);
    cudaGetSymbolAddress((void**)&gsum, g_gsum);
    cudaGetSymbolAddress((void**)&edge, g_edge);
    cudaGetSymbolAddress((void**)&batch, g_batch);
    cudaGetSymbolAddress((void**)&flag, g_flag);

    const int NT = 256;

    // ---- dtype-robust index conversion (handles int32 or int64 inputs) ----
    k_detect<<<1, 32>>>((const int*)edge_raw, flag);
    k_cvt<<<cdiv(2 * (long)EE, NT), NT>>>(edge_raw, 2 * EE, flag, edge);
    k_cvt<<<cdiv(NN, NT), NT>>>(batch_raw, NN, flag, batch);
    const int* row0 = edge;
    const int* col0 = edge + EE;

    // smem opt-in for the big GEMM tiles (sizes derived from the kernel's own TM rule)
    constexpr int SM_GIN  = gemm_smem(128, 128);   //  96 KB (TM=64)
    constexpr int SM_FFN1 = gemm_smem(128, 256);   // 144 KB (TM=32)
    constexpr int SM_FFN2 = gemm_smem(256, 128);   // 192 KB (TM=64)  <-- was 160 KB: OOB bug
    cudaFuncSetAttribute(k_gemm<128, 128, true,  false>, cudaFuncAttributeMaxDynamicSharedMemorySize, SM_GIN);
    cudaFuncSetAttribute(k_gemm<128, 128, false, false>, cudaFuncAttributeMaxDynamicSharedMemorySize, SM_GIN);
    cudaFuncSetAttribute(k_gemm<128, 256, true,  false>, cudaFuncAttributeMaxDynamicSharedMemorySize, SM_FFN1);
    cudaFuncSetAttribute(k_gemm<256, 128, false, true >, cudaFuncAttributeMaxDynamicSharedMemorySize, SM_FFN2);

    // ---- degrees / counts / edge weights / initial probability ----
    k_init<<<cdiv(NN, NT), NT>>>(deg, cnt);
    k_deg_scatter<<<cdiv(EE, NT), NT>>>(col0, deg);
    k_cnt_scatter<<<cdiv(NN, NT), NT>>>(batch, cnt);
    k_dinv<<<cdiv(NN, NT), NT>>>(dinv, deg);
    k_ew<<<cdiv(EE, NT), NT>>>(row0, col0, dinv, ew);
    k_prob<<<cdiv(NN, NT), NT>>>(batch, cnt, p);

    // ---- random walk PE ----
    for (int k = 0; k < WALKN; k++) {
        k_rwpre<<<cdiv(NN, NT), NT>>>(p, rw + (long)k * NN, np);
        if (k < WALKN - 1) {
            k_rwscat<<<cdiv(EE, NT), NT>>>(row0, col0, ew, p, np);
            k_rwcomb<<<cdiv(NN, NT), NT>>>(np, dinv, p);
        }
    }
    k_pe<<<cdiv(NN, 256), 256>>>(rw, pe_w, pe_b, pe);

    // ---- input projection (collapsed: constant part + PE part) ----
    k_base<<<1, HH>>>(emb, proj_w, proj_b, base);
    k_h0<<<cdiv((long)NN * HH, NT), NT>>>(pe, proj_w, base, h);

    // ---- GIN + FFN layers ----
    for (int i = 0; i < LL; i++) {
        k_copy4<<<cdiv(NN * HH / 4, NT), NT>>>((float4*)agg, (const float4*)h, NN * HH / 4);
        k_scatter<<<cdiv((long)EE * 32, NT), NT>>>(row0, col0, h, agg);
        k_gemm<128, 128, true,  false><<<592, 512, SM_GIN>>>(agg, gin_w1 + i * HH * HH, gin_b1 + i * HH, nullptr, t, NN);
        k_gemm<128, 128, false, false><<<592, 512, SM_GIN>>>(t,   gin_w2 + i * HH * HH, gin_b2 + i * HH, nullptr, z, NN);
        k_zero_stats<<<1, HH>>>(cs, cq);
        k_stats<<<512, HH>>>(z, cs, cq);
        k_murs<<<1, HH>>>(cs, cq, mu, rs);
        k_bn_relu_res<<<cdiv(NN * HH, NT), NT>>>(z, mu, rs, bn_g + i * HH, bn_b + i * HH, h);

        k_gemm<128, 256, true,  false><<<592, 512, SM_FFN1>>>(h, ffn_w1 + i * HH * 2 * HH, ffn_b1 + i * 2 * HH, nullptr, t, NN);
        k_gemm<256, 128, false, true ><<<592, 512, SM_FFN2>>>(t, ffn_w2 + i * 2 * HH * HH, ffn_b2 + i * HH, h, z, NN);
        k_zero_stats<<<1, HH>>>(cs, cq);
        k_stats<<<512, HH>>>(z, cs, cq);
        k_murs<<<1, HH>>>(cs, cq, mu, rs);
        k_bn<<<cdiv(NN * HH, NT), NT>>>(z, mu, rs, fbn_g + i * HH, fbn_b + i * HH, h);
    }

    // ---- global mean pool + MLP head ----
    k_zero_gsum<<<cdiv(GG * HH, NT), NT>>>(gsum);
    k_pool<<<512, HH>>>(h, batch, gsum);
    k_head<<<GG, HH>>>(gsum, cnt, ow1, ob1, ow2, ob2, out);
}